// round 1
// baseline (speedup 1.0000x reference)
#include <cuda_runtime.h>
#include <stdint.h>

#define EDGE_IN 19
#define WIDTH   64
#define NODE_IN 16
#define OUT     16
#define N_NODES_MAX 50000

// ---- shared memory layout (floats) ----
#define S_W0 0
#define S_B0 (S_W0 + EDGE_IN*WIDTH)        // 1216
#define S_W1 (S_B0 + WIDTH)                // 1280
#define S_B1 (S_W1 + WIDTH*WIDTH)          // 5376
#define S_W2 (S_B1 + WIDTH)                // 5440
#define S_B2 (S_W2 + WIDTH*WIDTH)          // 9536
#define S_LW (S_B2 + WIDTH)                // 9600
#define S_LB (S_LW + WIDTH*NODE_IN*OUT)    // 25984
#define S_ACT (S_LB + NODE_IN*OUT)         // 26240
#define SMEM_FLOATS (S_ACT + WIDTH*256)    // 26240 + 16384 = 42624
#define SMEM_BYTES (SMEM_FLOATS*4)         // 170496

// scatter-max accumulator (bits of float; init to -inf bits)
__device__ unsigned int g_agg[N_NODES_MAX * OUT];

__global__ void init_agg_kernel(int n) {
    int i = blockIdx.x * blockDim.x + threadIdx.x;
    if (i < n) g_agg[i] = 0xFF800000u;  // -inf
}

__global__ __launch_bounds__(256, 1)
void edge_kernel(const float* __restrict__ node_feats,
                 const int*   __restrict__ edge_index,
                 const float* __restrict__ edge_feats,
                 const float* __restrict__ w0, const float* __restrict__ b0,
                 const float* __restrict__ w1, const float* __restrict__ b1,
                 const float* __restrict__ w2, const float* __restrict__ b2,
                 const float* __restrict__ lw, const float* __restrict__ lb,
                 int E)
{
    extern __shared__ float s[];
    const int tid = threadIdx.x;

    // ---- cooperative weight load into smem (vectorized) ----
    {
        float4* d = (float4*)s;
        const float4* v;
        v = (const float4*)w0; for (int i = tid; i < (EDGE_IN*WIDTH)/4; i += 256) d[S_W0/4 + i] = v[i];
        v = (const float4*)b0; for (int i = tid; i < WIDTH/4;          i += 256) d[S_B0/4 + i] = v[i];
        v = (const float4*)w1; for (int i = tid; i < (WIDTH*WIDTH)/4;  i += 256) d[S_W1/4 + i] = v[i];
        v = (const float4*)b1; for (int i = tid; i < WIDTH/4;          i += 256) d[S_B1/4 + i] = v[i];
        v = (const float4*)w2; for (int i = tid; i < (WIDTH*WIDTH)/4;  i += 256) d[S_W2/4 + i] = v[i];
        v = (const float4*)b2; for (int i = tid; i < WIDTH/4;          i += 256) d[S_B2/4 + i] = v[i];
        v = (const float4*)lw; for (int i = tid; i < (WIDTH*NODE_IN*OUT)/4; i += 256) d[S_LW/4 + i] = v[i];
        v = (const float4*)lb; for (int i = tid; i < (NODE_IN*OUT)/4;  i += 256) d[S_LB/4 + i] = v[i];
    }
    __syncthreads();

    float* act = s + S_ACT;   // per-thread column: act[row*256 + tid]

    int e = blockIdx.x * 256 + tid;
    bool valid = (e < E);
    int ee = valid ? e : (E - 1);

    // stage this edge's features in own smem column (avoids local-mem arrays)
    #pragma unroll
    for (int k = 0; k < EDGE_IN; k++)
        act[k * 256 + tid] = edge_feats[(size_t)ee * EDGE_IN + k];

    float h[WIDTH];

    // ---- layer 0: EDGE_IN -> WIDTH, relu ----
    #pragma unroll
    for (int j = 0; j < WIDTH; j++) h[j] = s[S_B0 + j];
    #pragma unroll 1
    for (int k = 0; k < EDGE_IN; k++) {
        float x = act[k * 256 + tid];
        const float4* wr = (const float4*)(s + S_W0 + k * WIDTH);
        #pragma unroll
        for (int j = 0; j < WIDTH/4; j++) {
            float4 w = wr[j];
            h[4*j+0] = fmaf(x, w.x, h[4*j+0]);
            h[4*j+1] = fmaf(x, w.y, h[4*j+1]);
            h[4*j+2] = fmaf(x, w.z, h[4*j+2]);
            h[4*j+3] = fmaf(x, w.w, h[4*j+3]);
        }
    }
    #pragma unroll
    for (int j = 0; j < WIDTH; j++) act[j * 256 + tid] = fmaxf(h[j], 0.f);

    // ---- layer 1: WIDTH -> WIDTH, relu ----
    #pragma unroll
    for (int j = 0; j < WIDTH; j++) h[j] = s[S_B1 + j];
    #pragma unroll 1
    for (int k = 0; k < WIDTH; k++) {
        float x = act[k * 256 + tid];
        const float4* wr = (const float4*)(s + S_W1 + k * WIDTH);
        #pragma unroll
        for (int j = 0; j < WIDTH/4; j++) {
            float4 w = wr[j];
            h[4*j+0] = fmaf(x, w.x, h[4*j+0]);
            h[4*j+1] = fmaf(x, w.y, h[4*j+1]);
            h[4*j+2] = fmaf(x, w.z, h[4*j+2]);
            h[4*j+3] = fmaf(x, w.w, h[4*j+3]);
        }
    }
    #pragma unroll
    for (int j = 0; j < WIDTH; j++) act[j * 256 + tid] = fmaxf(h[j], 0.f);

    // ---- layer 2: WIDTH -> WIDTH, relu ----
    #pragma unroll
    for (int j = 0; j < WIDTH; j++) h[j] = s[S_B2 + j];
    #pragma unroll 1
    for (int k = 0; k < WIDTH; k++) {
        float x = act[k * 256 + tid];
        const float4* wr = (const float4*)(s + S_W2 + k * WIDTH);
        #pragma unroll
        for (int j = 0; j < WIDTH/4; j++) {
            float4 w = wr[j];
            h[4*j+0] = fmaf(x, w.x, h[4*j+0]);
            h[4*j+1] = fmaf(x, w.y, h[4*j+1]);
            h[4*j+2] = fmaf(x, w.z, h[4*j+2]);
            h[4*j+3] = fmaf(x, w.w, h[4*j+3]);
        }
    }
    #pragma unroll
    for (int j = 0; j < WIDTH; j++) act[j * 256 + tid] = fmaxf(h[j], 0.f);
    // act now holds h2 for this edge

    // ---- fused (h2 @ lin_w + lin_b) and einsum with src node feats ----
    int srcn = edge_index[ee];
    int dstn = edge_index[E + ee];

    float xi[NODE_IN];
    {
        const float4* nf = (const float4*)(node_feats + (size_t)srcn * NODE_IN);
        float4 a = nf[0], b = nf[1], c = nf[2], d4 = nf[3];
        xi[0]=a.x;  xi[1]=a.y;  xi[2]=a.z;  xi[3]=a.w;
        xi[4]=b.x;  xi[5]=b.y;  xi[6]=b.z;  xi[7]=b.w;
        xi[8]=c.x;  xi[9]=c.y;  xi[10]=c.z; xi[11]=c.w;
        xi[12]=d4.x; xi[13]=d4.y; xi[14]=d4.z; xi[15]=d4.w;
    }

    float msg[OUT];
    #pragma unroll
    for (int o = 0; o < OUT; o++) msg[o] = 0.f;

    #pragma unroll
    for (int i = 0; i < NODE_IN; i++) {
        float w[OUT];
        #pragma unroll
        for (int o4 = 0; o4 < OUT/4; o4++) {
            float4 bb = *(const float4*)(s + S_LB + i*OUT + 4*o4);
            w[4*o4+0] = bb.x; w[4*o4+1] = bb.y; w[4*o4+2] = bb.z; w[4*o4+3] = bb.w;
        }
        #pragma unroll 1
        for (int k = 0; k < WIDTH; k++) {
            float hh = act[k * 256 + tid];
            const float4* lwv = (const float4*)(s + S_LW + k*(NODE_IN*OUT) + i*OUT);
            #pragma unroll
            for (int o4 = 0; o4 < OUT/4; o4++) {
                float4 ww = lwv[o4];
                w[4*o4+0] = fmaf(hh, ww.x, w[4*o4+0]);
                w[4*o4+1] = fmaf(hh, ww.y, w[4*o4+1]);
                w[4*o4+2] = fmaf(hh, ww.z, w[4*o4+2]);
                w[4*o4+3] = fmaf(hh, ww.w, w[4*o4+3]);
            }
        }
        float xv = xi[i];
        #pragma unroll
        for (int o = 0; o < OUT; o++) msg[o] = fmaf(xv, w[o], msg[o]);
    }

    // ---- scatter max (bit-trick float atomic max, no return value -> REDG) ----
    if (valid) {
        unsigned int* slot = &g_agg[(size_t)dstn * OUT];
        #pragma unroll
        for (int o = 0; o < OUT; o++) {
            unsigned int b = __float_as_uint(msg[o]);
            if (b == 0x80000000u) b = 0u;  // canonicalize -0.0 -> +0.0
            if ((int)b >= 0) atomicMax((int*)(slot + o), (int)b);
            else             atomicMin(slot + o, b);
        }
    }
}

__global__ __launch_bounds__(256)
void node_kernel(const float* __restrict__ node_feats,
                 const float* __restrict__ root_w,
                 const float* __restrict__ bias,
                 float* __restrict__ out, int N)
{
    __shared__ float rw[NODE_IN * OUT];
    __shared__ float bs[OUT];
    int tid = threadIdx.x;
    if (tid < NODE_IN * OUT) rw[tid] = root_w[tid];
    if (tid < OUT) bs[tid] = bias[tid];
    __syncthreads();

    int n = blockIdx.x * 256 + tid;
    if (n >= N) return;

    float xi[NODE_IN];
    {
        const float4* nf = (const float4*)(node_feats + (size_t)n * NODE_IN);
        float4 a = nf[0], b = nf[1], c = nf[2], d4 = nf[3];
        xi[0]=a.x;  xi[1]=a.y;  xi[2]=a.z;  xi[3]=a.w;
        xi[4]=b.x;  xi[5]=b.y;  xi[6]=b.z;  xi[7]=b.w;
        xi[8]=c.x;  xi[9]=c.y;  xi[10]=c.z; xi[11]=c.w;
        xi[12]=d4.x; xi[13]=d4.y; xi[14]=d4.z; xi[15]=d4.w;
    }

    float o[OUT];
    #pragma unroll
    for (int j = 0; j < OUT; j++) o[j] = bs[j];
    #pragma unroll
    for (int i = 0; i < NODE_IN; i++) {
        float xv = xi[i];
        #pragma unroll
        for (int j = 0; j < OUT; j++) o[j] = fmaf(xv, rw[i*OUT + j], o[j]);
    }

    #pragma unroll
    for (int j = 0; j < OUT; j++) {
        unsigned int a = g_agg[(size_t)n * OUT + j];
        float av = (a == 0xFF800000u) ? 0.f : __uint_as_float(a);
        o[j] += av;
    }

    float4* ov = (float4*)(out + (size_t)n * OUT);
    ov[0] = make_float4(o[0],  o[1],  o[2],  o[3]);
    ov[1] = make_float4(o[4],  o[5],  o[6],  o[7]);
    ov[2] = make_float4(o[8],  o[9],  o[10], o[11]);
    ov[3] = make_float4(o[12], o[13], o[14], o[15]);
}

extern "C" void kernel_launch(void* const* d_in, const int* in_sizes, int n_in,
                              void* d_out, int out_size)
{
    const float* node_feats = (const float*)d_in[0];
    const int*   edge_index = (const int*)  d_in[1];
    const float* edge_feats = (const float*)d_in[2];
    const float* w0 = (const float*)d_in[3];
    const float* b0 = (const float*)d_in[4];
    const float* w1 = (const float*)d_in[5];
    const float* b1 = (const float*)d_in[6];
    const float* w2 = (const float*)d_in[7];
    const float* b2 = (const float*)d_in[8];
    const float* lw = (const float*)d_in[9];
    const float* lb = (const float*)d_in[10];
    const float* root_w = (const float*)d_in[11];
    const float* bias   = (const float*)d_in[12];

    int E = in_sizes[1] / 2;
    int N = in_sizes[0] / NODE_IN;

    cudaFuncSetAttribute(edge_kernel, cudaFuncAttributeMaxDynamicSharedMemorySize, SMEM_BYTES);

    init_agg_kernel<<<(N * OUT + 255) / 256, 256>>>(N * OUT);
    edge_kernel<<<(E + 255) / 256, 256, SMEM_BYTES>>>(
        node_feats, edge_index, edge_feats, w0, b0, w1, b1, w2, b2, lw, lb, E);
    node_kernel<<<(N + 255) / 256, 256>>>(node_feats, root_w, bias, (float*)d_out, N);
}

// round 4
// speedup vs baseline: 1.2307x; 1.2307x over previous
#include <cuda_runtime.h>
#include <stdint.h>

#define EDGE_IN 19
#define WIDTH   64
#define NODE_IN 16
#define OUT     16
#define N_NODES_MAX 50000
#define T 384      // threads per block
#define NBLK 148   // persistent blocks (~1 per SM)

// ---- shared memory layout (floats) ----
#define S_W0 0
#define S_B0 (S_W0 + EDGE_IN*WIDTH)        // 1216
#define S_W1 (S_B0 + WIDTH)                // 1280
#define S_B1 (S_W1 + WIDTH*WIDTH)          // 5376
#define S_W2 (S_B1 + WIDTH)                // 5440
#define S_B2 (S_W2 + WIDTH*WIDTH)          // 9536
#define S_LW (S_B2 + WIDTH)                // 9600
#define S_LB (S_LW + WIDTH*NODE_IN*OUT)    // 25984
#define S_ACT (S_LB + NODE_IN*OUT)         // 26240
#define SMEM_FLOATS (S_ACT + WIDTH*T)      // 50816
#define SMEM_BYTES (SMEM_FLOATS*4)         // 203264

typedef unsigned long long u64;

// Packed dual-fp32 FMA (Blackwell f32x2 path; ptxas never emits this from C++)
__device__ __forceinline__ u64 ffma2(u64 a, u64 b, u64 c) {
    u64 d;
    asm("fma.rn.f32x2 %0, %1, %2, %3;" : "=l"(d) : "l"(a), "l"(b), "l"(c));
    return d;
}
__device__ __forceinline__ u64 pack2(float x) {
    u64 r;
    asm("mov.b64 %0, {%1, %1};" : "=l"(r) : "f"(x));
    return r;
}
__device__ __forceinline__ void unpack2(u64 v, float& lo, float& hi) {
    asm("mov.b64 {%0, %1}, %2;" : "=f"(lo), "=f"(hi) : "l"(v));
}
// monotone float->int ordering map (branch-free scatter-max via RED.MAX.S32)
__device__ __forceinline__ int ford(float f) {
    int b = __float_as_int(f);
    return b >= 0 ? b : (b ^ 0x7fffffff);
}

// scatter-max accumulator in ordered-int space; init = INT_MIN (below any float)
__device__ int g_agg[N_NODES_MAX * OUT];

__global__ void init_agg_kernel(int n) {
    int i = blockIdx.x * blockDim.x + threadIdx.x;
    if (i < n) g_agg[i] = (int)0x80000000;
}

__global__ __launch_bounds__(T, 1)
void edge_kernel(const float* __restrict__ node_feats,
                 const int*   __restrict__ edge_index,
                 const float* __restrict__ edge_feats,
                 const float* __restrict__ w0, const float* __restrict__ b0,
                 const float* __restrict__ w1, const float* __restrict__ b1,
                 const float* __restrict__ w2, const float* __restrict__ b2,
                 const float* __restrict__ lw, const float* __restrict__ lb,
                 int E)
{
    extern __shared__ float s[];
    const int tid = threadIdx.x;

    // ---- cooperative weight load into smem (once per persistent block) ----
    {
        float4* d = (float4*)s;
        const float4* v;
        v = (const float4*)w0; for (int i = tid; i < (EDGE_IN*WIDTH)/4; i += T) d[S_W0/4 + i] = v[i];
        v = (const float4*)b0; for (int i = tid; i < WIDTH/4;          i += T) d[S_B0/4 + i] = v[i];
        v = (const float4*)w1; for (int i = tid; i < (WIDTH*WIDTH)/4;  i += T) d[S_W1/4 + i] = v[i];
        v = (const float4*)b1; for (int i = tid; i < WIDTH/4;          i += T) d[S_B1/4 + i] = v[i];
        v = (const float4*)w2; for (int i = tid; i < (WIDTH*WIDTH)/4;  i += T) d[S_W2/4 + i] = v[i];
        v = (const float4*)b2; for (int i = tid; i < WIDTH/4;          i += T) d[S_B2/4 + i] = v[i];
        v = (const float4*)lw; for (int i = tid; i < (WIDTH*NODE_IN*OUT)/4; i += T) d[S_LW/4 + i] = v[i];
        v = (const float4*)lb; for (int i = tid; i < (NODE_IN*OUT)/4;  i += T) d[S_LB/4 + i] = v[i];
    }
    __syncthreads();

    float* act = s + S_ACT;   // per-thread column: act[row*T + tid]
    const int ntiles = (E + T - 1) / T;

    for (int tile = blockIdx.x; tile < ntiles; tile += gridDim.x) {
        int e = tile * T + tid;
        bool valid = (e < E);
        int ee = valid ? e : (E - 1);

        // stage this edge's features in own smem column
        #pragma unroll
        for (int k = 0; k < EDGE_IN; k++)
            act[k * T + tid] = edge_feats[(size_t)ee * EDGE_IN + k];

        u64 h2[WIDTH/2];

        // ---- MLP layer macro: K inputs (in act rows) -> 64 outputs, relu, back to act ----
        #define LAYER(K, SW, SB)                                                     \
        {                                                                            \
            const u64* __restrict__ bb = (const u64*)(s + (SB));                     \
            _Pragma("unroll")                                                        \
            for (int j = 0; j < WIDTH/2; j++) h2[j] = bb[j];                         \
            _Pragma("unroll 1")                                                      \
            for (int k = 0; k < (K); k++) {                                          \
                u64 x = pack2(act[k * T + tid]);                                     \
                const ulonglong2* __restrict__ wr =                                  \
                    (const ulonglong2*)(s + (SW) + k * WIDTH);                       \
                _Pragma("unroll")                                                    \
                for (int j = 0; j < WIDTH/4; j++) {                                  \
                    ulonglong2 w = wr[j];                                            \
                    h2[2*j+0] = ffma2(x, w.x, h2[2*j+0]);                            \
                    h2[2*j+1] = ffma2(x, w.y, h2[2*j+1]);                            \
                }                                                                    \
            }                                                                        \
            _Pragma("unroll")                                                        \
            for (int j = 0; j < WIDTH/2; j++) {                                      \
                float lo, hi; unpack2(h2[j], lo, hi);                                \
                act[(2*j+0) * T + tid] = fmaxf(lo, 0.f);                             \
                act[(2*j+1) * T + tid] = fmaxf(hi, 0.f);                             \
            }                                                                        \
        }

        LAYER(EDGE_IN, S_W0, S_B0)
        LAYER(WIDTH,   S_W1, S_B1)
        LAYER(WIDTH,   S_W2, S_B2)
        #undef LAYER
        // act rows now hold h2 (post layer-2 relu)

        // ---- fused (h2 @ lin_w + lin_b) contracted with src node feats ----
        int srcn = edge_index[ee];
        int dstn = edge_index[E + ee];

        u64 xp[NODE_IN];
        {
            const float4* nf = (const float4*)(node_feats + (size_t)srcn * NODE_IN);
            float4 a = nf[0], b = nf[1], c = nf[2], d4 = nf[3];
            xp[0]=pack2(a.x);  xp[1]=pack2(a.y);  xp[2]=pack2(a.z);  xp[3]=pack2(a.w);
            xp[4]=pack2(b.x);  xp[5]=pack2(b.y);  xp[6]=pack2(b.z);  xp[7]=pack2(b.w);
            xp[8]=pack2(c.x);  xp[9]=pack2(c.y);  xp[10]=pack2(c.z); xp[11]=pack2(c.w);
            xp[12]=pack2(d4.x);xp[13]=pack2(d4.y);xp[14]=pack2(d4.z);xp[15]=pack2(d4.w);
        }

        // bias part: msg[o] = sum_i x_i * lb[i,o]
        u64 msg2[OUT/2];
        {
            #pragma unroll
            for (int o = 0; o < OUT/2; o++) msg2[o] = 0ull;
            const ulonglong2* __restrict__ lbv = (const ulonglong2*)(s + S_LB);
            #pragma unroll
            for (int i = 0; i < NODE_IN; i++) {
                #pragma unroll
                for (int o4 = 0; o4 < OUT/4; o4++) {
                    ulonglong2 w = lbv[i * (OUT/4) + o4];
                    msg2[2*o4+0] = ffma2(xp[i], w.x, msg2[2*o4+0]);
                    msg2[2*o4+1] = ffma2(xp[i], w.y, msg2[2*o4+1]);
                }
            }
        }

        // k-outer: t[o] = sum_i x_i*lw[k,i,o]; msg[o] += h_k*t[o]
        const ulonglong2* __restrict__ lwv = (const ulonglong2*)(s + S_LW);
        #pragma unroll 1
        for (int k = 0; k < WIDTH; k++) {
            u64 hp = pack2(act[k * T + tid]);
            u64 t2[OUT/2];
            #pragma unroll
            for (int o = 0; o < OUT/2; o++) t2[o] = 0ull;
            const ulonglong2* __restrict__ lwk = lwv + k * (NODE_IN*OUT/4);
            #pragma unroll
            for (int i = 0; i < NODE_IN; i++) {
                #pragma unroll
                for (int o4 = 0; o4 < OUT/4; o4++) {
                    ulonglong2 w = lwk[i * (OUT/4) + o4];
                    t2[2*o4+0] = ffma2(xp[i], w.x, t2[2*o4+0]);
                    t2[2*o4+1] = ffma2(xp[i], w.y, t2[2*o4+1]);
                }
            }
            #pragma unroll
            for (int o = 0; o < OUT/2; o++) msg2[o] = ffma2(hp, t2[o], msg2[o]);
        }

        // ---- scatter max: branch-free ordered-int RED.MAX ----
        if (valid) {
            int* slot = &g_agg[(size_t)dstn * OUT];
            #pragma unroll
            for (int o = 0; o < OUT/2; o++) {
                float lo, hi; unpack2(msg2[o], lo, hi);
                atomicMax(slot + 2*o + 0, ford(lo));
                atomicMax(slot + 2*o + 1, ford(hi));
            }
        }
    }
}

__global__ __launch_bounds__(256)
void node_kernel(const float* __restrict__ node_feats,
                 const float* __restrict__ root_w,
                 const float* __restrict__ bias,
                 float* __restrict__ out, int N)
{
    __shared__ float rw[NODE_IN * OUT];
    __shared__ float bs[OUT];
    int tid = threadIdx.x;
    if (tid < NODE_IN * OUT) rw[tid] = root_w[tid];
    if (tid < OUT) bs[tid] = bias[tid];
    __syncthreads();

    int n = blockIdx.x * 256 + tid;
    if (n >= N) return;

    float xi[NODE_IN];
    {
        const float4* nf = (const float4*)(node_feats + (size_t)n * NODE_IN);
        float4 a = nf[0], b = nf[1], c = nf[2], d4 = nf[3];
        xi[0]=a.x;  xi[1]=a.y;  xi[2]=a.z;  xi[3]=a.w;
        xi[4]=b.x;  xi[5]=b.y;  xi[6]=b.z;  xi[7]=b.w;
        xi[8]=c.x;  xi[9]=c.y;  xi[10]=c.z; xi[11]=c.w;
        xi[12]=d4.x; xi[13]=d4.y; xi[14]=d4.z; xi[15]=d4.w;
    }

    float o[OUT];
    #pragma unroll
    for (int j = 0; j < OUT; j++) o[j] = bs[j];
    #pragma unroll
    for (int i = 0; i < NODE_IN; i++) {
        float xv = xi[i];
        #pragma unroll
        for (int j = 0; j < OUT; j++) o[j] = fmaf(xv, rw[i*OUT + j], o[j]);
    }

    #pragma unroll
    for (int j = 0; j < OUT; j++) {
        int a = g_agg[(size_t)n * OUT + j];
        float av;
        if (a == (int)0x80000000) av = 0.f;                 // no in-edges
        else av = __int_as_float(a >= 0 ? a : (a ^ 0x7fffffff));
        o[j] += av;
    }

    float4* ov = (float4*)(out + (size_t)n * OUT);
    ov[0] = make_float4(o[0],  o[1],  o[2],  o[3]);
    ov[1] = make_float4(o[4],  o[5],  o[6],  o[7]);
    ov[2] = make_float4(o[8],  o[9],  o[10], o[11]);
    ov[3] = make_float4(o[12], o[13], o[14], o[15]);
}

extern "C" void kernel_launch(void* const* d_in, const int* in_sizes, int n_in,
                              void* d_out, int out_size)
{
    const float* node_feats = (const float*)d_in[0];
    const int*   edge_index = (const int*)  d_in[1];
    const float* edge_feats = (const float*)d_in[2];
    const float* w0 = (const float*)d_in[3];
    const float* b0 = (const float*)d_in[4];
    const float* w1 = (const float*)d_in[5];
    const float* b1 = (const float*)d_in[6];
    const float* w2 = (const float*)d_in[7];
    const float* b2 = (const float*)d_in[8];
    const float* lw = (const float*)d_in[9];
    const float* lb = (const float*)d_in[10];
    const float* root_w = (const float*)d_in[11];
    const float* bias   = (const float*)d_in[12];

    int E = in_sizes[1] / 2;
    int N = in_sizes[0] / NODE_IN;

    cudaFuncSetAttribute(edge_kernel, cudaFuncAttributeMaxDynamicSharedMemorySize, SMEM_BYTES);

    init_agg_kernel<<<(N * OUT + 255) / 256, 256>>>(N * OUT);

    int ntiles = (E + T - 1) / T;
    int grid = ntiles < NBLK ? ntiles : NBLK;
    edge_kernel<<<grid, T, SMEM_BYTES>>>(
        node_feats, edge_index, edge_feats, w0, b0, w1, b1, w2, b2, lw, lb, E);

    node_kernel<<<(N + 255) / 256, 256>>>(node_feats, root_w, bias, (float*)d_out, N);
}